// round 10
// baseline (speedup 1.0000x reference)
#include <cuda_runtime.h>
#include <math.h>
#include <stdint.h>

#define NN 100000
#define NE 1600000
#define NB 64
#define FI 16
#define HD 128
#define GF 8
#define F19 19
#define F20 20
#define BN_EPS 1e-5f
#define SCAN_BS 1024
#define SCAN_NBLK ((NN + SCAN_BS - 1) / SCAN_BS)   // 98
#define APS 72                                      // smem row stride (floats)
#define TG_SMEM ((2 * 128 * APS + 128) * 4)         // 74240 B

typedef unsigned long long ull;

// ---------------- scratch (device globals: allocation-free) ----------------
__device__ float g_x19 [NN * F20];
__device__ float g_xa19[NN * F20];
__device__ float g_h   [NN * HD];
__device__ float g_xagg[NN * HD];
__device__ float g_xA  [NN * HD];
__device__ float g_xB  [NN * HD];
__device__ float g_stats[2 * HD];
__device__ float g_coef [2 * HD];
__device__ int   g_gstart[NB + 1];
__device__ float g_pooled[NB * 2 * HD];
__device__ float g_wtP[HD * 2 * HD];   // packed W^T tf32 hi/lo: [slab][n][2*kk+h]
// CSR scratch
__device__ int g_deg[NN];
__device__ int g_rowstart[NN + 1];
__device__ int g_cursor[NN];
__device__ int g_esrc[NE];
__device__ int g_bsum[SCAN_NBLK];

// ---------------- helpers ----------------
__device__ __forceinline__ float elu01(float v) {
    return v > 0.f ? v : 0.1f * expm1f(v);
}
__device__ __forceinline__ void ffma2(ull& d, ull a, ull b) {
    asm("fma.rn.f32x2 %0, %1, %2, %0;" : "+l"(d) : "l"(a), "l"(b));
}
__device__ __forceinline__ ull dup2(float a) {
    ull r; asm("mov.b64 %0, {%1, %1};" : "=l"(r) : "f"(a)); return r;
}
__device__ __forceinline__ ull pk2(float x, float y) {
    ull r; asm("mov.b64 %0, {%1, %2};" : "=l"(r) : "f"(x), "f"(y)); return r;
}
__device__ __forceinline__ float2 upk(ull v) {
    float2 f; asm("mov.b64 {%0, %1}, %2;" : "=f"(f.x), "=f"(f.y) : "l"(v)); return f;
}
__device__ __forceinline__ float to_tf32(float x) {
    float r; asm("cvt.rna.tf32.f32 %0, %1;" : "=f"(r) : "f"(x)); return r;
}
// m16n8k8 tf32 MMA, fp32 accum (baseline PTX, no sm_103a feature needed)
__device__ __forceinline__ void mma8(float* d, float a0, float a1, float a2, float a3,
                                     float b0, float b1) {
    asm("mma.sync.aligned.m16n8k8.row.col.f32.tf32.tf32.f32 "
        "{%0,%1,%2,%3}, {%4,%5,%6,%7}, {%8,%9}, {%0,%1,%2,%3};"
        : "+f"(d[0]), "+f"(d[1]), "+f"(d[2]), "+f"(d[3])
        : "r"(__float_as_uint(a0)), "r"(__float_as_uint(a1)),
          "r"(__float_as_uint(a2)), "r"(__float_as_uint(a3)),
          "r"(__float_as_uint(b0)), "r"(__float_as_uint(b1)));
}

// ---------------- CSR build ----------------
__global__ void k_zerodeg() {
    int i = blockIdx.x * blockDim.x + threadIdx.x;
    if (i < NN) g_deg[i] = 0;
}
__global__ void k_deg(const int* __restrict__ dst) {
    int e = blockIdx.x * blockDim.x + threadIdx.x;
    if (e < NE) atomicAdd(&g_deg[dst[e]], 1);
}
__global__ void k_scanA() {
    __shared__ int s[SCAN_BS];
    int i = blockIdx.x * SCAN_BS + threadIdx.x;
    int v = (i < NN) ? g_deg[i] : 0;
    s[threadIdx.x] = v;
    __syncthreads();
#pragma unroll
    for (int off = 1; off < SCAN_BS; off <<= 1) {
        int t = (threadIdx.x >= off) ? s[threadIdx.x - off] : 0;
        __syncthreads();
        s[threadIdx.x] += t;
        __syncthreads();
    }
    if (i < NN) g_rowstart[i] = s[threadIdx.x] - v;
    if (threadIdx.x == SCAN_BS - 1) g_bsum[blockIdx.x] = s[SCAN_BS - 1];
}
__global__ void k_scanB() {   // <<<1,32>>> warp scan
    int lane = threadIdx.x;
    int carry = 0;
    for (int b0 = 0; b0 < SCAN_NBLK; b0 += 32) {
        int i = b0 + lane;
        int orig = (i < SCAN_NBLK) ? g_bsum[i] : 0;
        int v = orig;
#pragma unroll
        for (int o = 1; o < 32; o <<= 1) {
            int t = __shfl_up_sync(0xFFFFFFFFu, v, o);
            if (lane >= o) v += t;
        }
        int total = __shfl_sync(0xFFFFFFFFu, v, 31);
        if (i < SCAN_NBLK) g_bsum[i] = v - orig + carry;
        carry += total;
    }
    if (lane == 0) g_rowstart[NN] = NE;
}
__global__ void k_scanC() {
    int i = blockIdx.x * blockDim.x + threadIdx.x;
    if (i < NN) {
        int r = g_rowstart[i] + g_bsum[i / SCAN_BS];
        g_rowstart[i] = r;
        g_cursor[i] = r;
    }
}
__global__ void k_fill(const int* __restrict__ src, const int* __restrict__ dst) {
    int e = blockIdx.x * blockDim.x + threadIdx.x;
    if (e < NE) {
        int pos = atomicAdd(&g_cursor[dst[e]], 1);
        g_esrc[pos] = src[e];
    }
}

// ---------------- feature prep + gather aggregation ----------------
__global__ void k_concat(const float* __restrict__ h0, const float* __restrict__ coord) {
    int i = blockIdx.x * blockDim.x + threadIdx.x;
    if (i >= NN * F20) return;
    int n = i / F20, j = i - n * F20;
    float v = 0.f;
    if (j < FI)        v = h0[n * FI + j];
    else if (j < F19)  v = coord[n * 3 + (j - FI)];
    g_x19[i] = v;
}

__global__ void k_gather19() {
    int node = blockIdx.x * 8 + (threadIdx.x >> 5);
    int lane = threadIdx.x & 31;
    if (node >= NN || lane >= 5) return;
    int st = g_rowstart[node], en = g_rowstart[node + 1];
    float4 v = *(const float4*)&g_x19[node * F20 + lane * 4];
    for (int e = st; e < en; e++) {
        int s = g_esrc[e];
        float4 u = *(const float4*)&g_x19[s * F20 + lane * 4];
        v.x += u.x; v.y += u.y; v.z += u.z; v.w += u.w;
    }
    *(float4*)&g_xa19[node * F20 + lane * 4] = v;
}

__global__ void k_gatherH(const float* __restrict__ x, float* __restrict__ xa) {
    int node = blockIdx.x * 8 + (threadIdx.x >> 5);
    if (node >= NN) return;
    int lane = threadIdx.x & 31;
    int st = g_rowstart[node], en = g_rowstart[node + 1];
    float4 v0 = *(const float4*)&x[node * HD + lane * 4];
    float4 v1 = make_float4(0.f, 0.f, 0.f, 0.f);
    int e = st;
    for (; e + 1 < en; e += 2) {
        int s0 = g_esrc[e], s1 = g_esrc[e + 1];
        float4 u0 = *(const float4*)&x[s0 * HD + lane * 4];
        float4 u1 = *(const float4*)&x[s1 * HD + lane * 4];
        v0.x += u0.x; v0.y += u0.y; v0.z += u0.z; v0.w += u0.w;
        v1.x += u1.x; v1.y += u1.y; v1.z += u1.z; v1.w += u1.w;
    }
    if (e < en) {
        int s0 = g_esrc[e];
        float4 u0 = *(const float4*)&x[s0 * HD + lane * 4];
        v0.x += u0.x; v0.y += u0.y; v0.z += u0.z; v0.w += u0.w;
    }
    v0.x += v1.x; v0.y += v1.y; v0.z += v1.z; v0.w += v1.w;
    *(float4*)&xa[node * HD + lane * 4] = v0;
}

__global__ void k_zerostats() { g_stats[threadIdx.x] = 0.f; }  // <<<1,256>>>

__global__ void k_stats(const float* __restrict__ x) {   // <<<512,128>>>
    int c = threadIdx.x;
    int nblk = gridDim.x;
    int per = (NN + nblk - 1) / nblk;
    int r0 = blockIdx.x * per;
    int r1 = r0 + per; if (r1 > NN) r1 = NN;
    float s = 0.f, q = 0.f;
    for (int r = r0; r < r1; r++) {
        float v = x[r * HD + c];
        s += v; q += v * v;
    }
    atomicAdd(&g_stats[c], s);
    atomicAdd(&g_stats[128 + c], q);
}

// W[128,128] -> packed transposed tf32 hi/lo: g_wtP[slab][n][2*kk+h]
__global__ void k_prepW(const float* __restrict__ W) {   // <<<64,256>>>
    int i = blockIdx.x * blockDim.x + threadIdx.x;
    if (i >= HD * HD) return;
    int k = i >> 7, n = i & 127;
    float w = W[i];
    float h = to_tf32(w);
    float l = to_tf32(w - h);
    int slab = k >> 5, kk = k & 31;
    float* dst = &g_wtP[((slab * 128 + n) * 64) + 2 * kk];
    dst[0] = h;
    dst[1] = l;
}

// ---------------- tf32 mma.sync 3x-split GEMM ----------------
// out[M,128] = act(A[M,128]) @ W + bias ; 128x128 block tile, 4 warps (64x64 warp tile)
template <bool TRANS_A, bool ELU>
__global__ void __launch_bounds__(128, 2)
k_tgemm(const float* __restrict__ A, const float* __restrict__ bias,
        float* __restrict__ out) {
    extern __shared__ float sm[];
    float* Ap = sm;                    // [128][APS]  (2*32 used + pad)
    float* Bp = sm + 128 * APS;        // [128][APS]
    float* s_bias = sm + 2 * 128 * APS;

    const int tid = threadIdx.x;
    const int wid = tid >> 5, lane = tid & 31;
    const int g = lane >> 2, c = lane & 3;
    const int wm = wid >> 1, wn = wid & 1;
    const int m0 = blockIdx.x * 128;

    s_bias[tid] = bias[tid];

    float acc[4][8][4];
#pragma unroll
    for (int mi = 0; mi < 4; mi++)
#pragma unroll
        for (int nf = 0; nf < 8; nf++)
#pragma unroll
            for (int j = 0; j < 4; j++) acc[mi][nf][j] = 0.f;

    for (int slab = 0; slab < 4; slab++) {
        const int k0 = slab * 32;
        // ---- A slab fill: thread owns row tid; hi/lo interleave ----
        {
            const int r = tid, grow = m0 + r;
#pragma unroll
            for (int j = 0; j < 8; j++) {
                float4 v = make_float4(0.f, 0.f, 0.f, 0.f);
                if (grow < NN) v = *(const float4*)&A[(size_t)grow * HD + k0 + j * 4];
                if (TRANS_A) {
                    float4 ca = *(const float4*)&g_coef[k0 + j * 4];
                    float4 cb = *(const float4*)&g_coef[128 + k0 + j * 4];
                    v.x = fmaxf(fmaf(ca.x, v.x, cb.x), 0.f);
                    v.y = fmaxf(fmaf(ca.y, v.y, cb.y), 0.f);
                    v.z = fmaxf(fmaf(ca.z, v.z, cb.z), 0.f);
                    v.w = fmaxf(fmaf(ca.w, v.w, cb.w), 0.f);
                }
                float hx = to_tf32(v.x), lx = to_tf32(v.x - hx);
                float hy = to_tf32(v.y), ly = to_tf32(v.y - hy);
                float hz = to_tf32(v.z), lz = to_tf32(v.z - hz);
                float hw = to_tf32(v.w), lw = to_tf32(v.w - hw);
                *(float4*)&Ap[r * APS + j * 8]     = make_float4(hx, lx, hy, ly);
                *(float4*)&Ap[r * APS + j * 8 + 4] = make_float4(hz, lz, hw, lw);
            }
        }
        // ---- B slab fill: straight copy of packed weights ----
        {
            const float* src = g_wtP + slab * 128 * 64;
#pragma unroll
            for (int t = 0; t < 16; t++) {
                int idx = tid + t * 128;           // float4 units, 0..2047
                int n = idx >> 4, u4 = idx & 15;
                *(float4*)&Bp[n * APS + u4 * 4] = *(const float4*)&src[n * 64 + u4 * 4];
            }
        }
        __syncthreads();

#pragma unroll
        for (int chunk = 0; chunk < 4; chunk++) {
            const int kk0 = chunk * 8;
            float2 b0p[8], b1p[8];   // .x = hi, .y = lo
#pragma unroll
            for (int nf = 0; nf < 8; nf++) {
                int nr = wn * 64 + nf * 8 + g;
                b0p[nf] = *(const float2*)&Bp[nr * APS + 2 * (kk0 + c)];
                b1p[nf] = *(const float2*)&Bp[nr * APS + 2 * (kk0 + c + 4)];
            }
#pragma unroll
            for (int mi = 0; mi < 4; mi++) {
                int r0 = wm * 64 + mi * 16 + g;
                float2 a0 = *(const float2*)&Ap[r0 * APS + 2 * (kk0 + c)];
                float2 a2 = *(const float2*)&Ap[r0 * APS + 2 * (kk0 + c + 4)];
                float2 a1 = *(const float2*)&Ap[(r0 + 8) * APS + 2 * (kk0 + c)];
                float2 a3 = *(const float2*)&Ap[(r0 + 8) * APS + 2 * (kk0 + c + 4)];
#pragma unroll
                for (int nf = 0; nf < 8; nf++) {
                    mma8(acc[mi][nf], a0.x, a1.x, a2.x, a3.x, b0p[nf].x, b1p[nf].x);
                    mma8(acc[mi][nf], a0.x, a1.x, a2.x, a3.x, b0p[nf].y, b1p[nf].y);
                    mma8(acc[mi][nf], a0.y, a1.y, a2.y, a3.y, b0p[nf].x, b1p[nf].x);
                }
            }
        }
        __syncthreads();
    }

    // ---- epilogue ----
#pragma unroll
    for (int mi = 0; mi < 4; mi++) {
        int row0 = m0 + wm * 64 + mi * 16 + g;
        int row1 = row0 + 8;
#pragma unroll
        for (int nf = 0; nf < 8; nf++) {
            int col = wn * 64 + nf * 8 + 2 * c;
            float bx = s_bias[col], by = s_bias[col + 1];
            if (row0 < NN) {
                float v0 = acc[mi][nf][0] + bx;
                float v1 = acc[mi][nf][1] + by;
                if (ELU) { v0 = elu01(v0); v1 = elu01(v1); }
                *(float2*)&out[(size_t)row0 * HD + col] = make_float2(v0, v1);
            }
            if (row1 < NN) {
                float v2 = acc[mi][nf][2] + bx;
                float v3 = acc[mi][nf][3] + by;
                if (ELU) { v2 = elu01(v2); v3 = elu01(v3); }
                *(float2*)&out[(size_t)row1 * HD + col] = make_float2(v2, v3);
            }
        }
    }
}

// ---------------- FFMA2 GEMM (layer-0, K=19) ----------------
__device__ __forceinline__ void ld_tiles(const float* __restrict__ A, int lda, int K,
                                         const float* __restrict__ W,
                                         int m0, int k0, int tid,
                                         float4* pa, float4* pw) {
#pragma unroll
    for (int p = 0; p < 2; p++) {
        int idx = tid * 2 + p;
        int r = idx >> 2, kq = idx & 3;
        int gk = k0 + kq * 4, grow = m0 + r;
        float4 v = make_float4(0.f, 0.f, 0.f, 0.f);
        if (grow < NN && gk < K) v = *(const float4*)&A[(size_t)grow * lda + gk];
        pa[p] = v;
        int kk = idx >> 5, n4 = idx & 31;
        float4 w = make_float4(0.f, 0.f, 0.f, 0.f);
        if (k0 + kk < K) w = *(const float4*)&W[(size_t)(k0 + kk) * HD + n4 * 4];
        pw[p] = w;
    }
}
__device__ __forceinline__ void st_tiles(float* __restrict__ As, float* __restrict__ Bs,
                                         int tid, const float4* pa, const float4* pw) {
#pragma unroll
    for (int p = 0; p < 2; p++) {
        int idx = tid * 2 + p;
        int r = idx >> 2, kq = idx & 3;
        float4 v = pa[p];
        As[(kq * 4 + 0) * 128 + r] = v.x;
        As[(kq * 4 + 1) * 128 + r] = v.y;
        As[(kq * 4 + 2) * 128 + r] = v.z;
        As[(kq * 4 + 3) * 128 + r] = v.w;
        int kk = idx >> 5, n4 = idx & 31;
        *(float4*)&Bs[kk * 128 + n4 * 4] = pw[p];
    }
}

__global__ void __launch_bounds__(256, 2)
k_gemm19(const float* __restrict__ A, const float* __restrict__ W,
         const float* __restrict__ bias, float* __restrict__ out) {
    __shared__ float As[2][16 * 128];
    __shared__ float Bs[2][16 * 128];
    const int K = F19, lda = F20;
    const int tid = threadIdx.x;
    const int tx = tid & 15;
    const int ty = tid >> 4;
    const int m0 = blockIdx.x * 128;

    ull acc[8][4];
#pragma unroll
    for (int r = 0; r < 8; r++)
#pragma unroll
        for (int c = 0; c < 4; c++) acc[r][c] = 0ull;

    const int nkt = 2;
    float4 pa[2], pw[2];
    ld_tiles(A, lda, K, W, m0, 0, tid, pa, pw);
    st_tiles(As[0], Bs[0], tid, pa, pw);
    __syncthreads();

    for (int kt = 0; kt < nkt; kt++) {
        const float* Ac = As[kt & 1];
        const float* Bc = Bs[kt & 1];
        if (kt + 1 < nkt) ld_tiles(A, lda, K, W, m0, 16, tid, pa, pw);
#pragma unroll
        for (int k = 0; k < 16; k++) {
            float4 a0 = *(const float4*)&Ac[k * 128 + ty * 8];
            float4 a1 = *(const float4*)&Ac[k * 128 + ty * 8 + 4];
            float4 b0 = *(const float4*)&Bc[k * 128 + tx * 8];
            float4 b1 = *(const float4*)&Bc[k * 128 + tx * 8 + 4];
            ull bp0 = pk2(b0.x, b0.y), bp1 = pk2(b0.z, b0.w);
            ull bp2 = pk2(b1.x, b1.y), bp3 = pk2(b1.z, b1.w);
            float ar[8] = {a0.x, a0.y, a0.z, a0.w, a1.x, a1.y, a1.z, a1.w};
#pragma unroll
            for (int r = 0; r < 8; r++) {
                ull ap = dup2(ar[r]);
                ffma2(acc[r][0], ap, bp0);
                ffma2(acc[r][1], ap, bp1);
                ffma2(acc[r][2], ap, bp2);
                ffma2(acc[r][3], ap, bp3);
            }
        }
        if (kt + 1 < nkt) st_tiles(As[1], Bs[1], tid, pa, pw);
        __syncthreads();
    }

    float4 bb0 = *(const float4*)&bias[tx * 8];
    float4 bb1 = *(const float4*)&bias[tx * 8 + 4];
    float bv[8] = {bb0.x, bb0.y, bb0.z, bb0.w, bb1.x, bb1.y, bb1.z, bb1.w};
#pragma unroll
    for (int r = 0; r < 8; r++) {
        int grow = m0 + ty * 8 + r;
        if (grow < NN) {
            float2 p0 = upk(acc[r][0]), p1 = upk(acc[r][1]);
            float2 p2 = upk(acc[r][2]), p3 = upk(acc[r][3]);
            float v[8] = {p0.x, p0.y, p1.x, p1.y, p2.x, p2.y, p3.x, p3.y};
#pragma unroll
            for (int c = 0; c < 8; c++) v[c] += bv[c];
            *(float4*)&out[(size_t)grow * HD + tx * 8]     = make_float4(v[0], v[1], v[2], v[3]);
            *(float4*)&out[(size_t)grow * HD + tx * 8 + 4] = make_float4(v[4], v[5], v[6], v[7]);
        }
    }
}

// ---------------- BN coef / pooling / classifier ----------------
__global__ void k_bncoef(const float* __restrict__ gm, const float* __restrict__ bt) {
    int c = threadIdx.x;  // <<<1,128>>>
    float mean = g_stats[c] * (1.f / NN);
    float var = g_stats[128 + c] * (1.f / NN) - mean * mean;
    float a = gm[c] * rsqrtf(var + BN_EPS);
    g_coef[c] = a;
    g_coef[128 + c] = bt[c] - mean * a;
}

__global__ void k_bounds(const int* __restrict__ batch) {
    int i = blockIdx.x * blockDim.x + threadIdx.x;
    if (i >= NN) return;
    int cur = batch[i];
    int prev = (i == 0) ? -1 : batch[i - 1];
    for (int g = prev + 1; g <= cur; ++g) g_gstart[g] = i;
    if (i == NN - 1)
        for (int g = cur + 1; g <= NB; ++g) g_gstart[g] = NN;
}

__global__ void k_pool(const float* __restrict__ x) {
    __shared__ float ps[4][128];
    __shared__ float pm[4][128];
    int b = blockIdx.x;
    int rg = threadIdx.x >> 7, c = threadIdx.x & 127;
    int st = g_gstart[b], en = g_gstart[b + 1];
    float s = 0.f, m = -INFINITY;
    for (int r = st + rg; r < en; r += 4) {
        float v = x[r * HD + c];
        s += v;
        m = fmaxf(m, v);
    }
    ps[rg][c] = s;
    pm[rg][c] = m;
    __syncthreads();
    if (rg == 0) {
        float ss = ps[0][c] + ps[1][c] + ps[2][c] + ps[3][c];
        float mm = fmaxf(fmaxf(pm[0][c], pm[1][c]), fmaxf(pm[2][c], pm[3][c]));
        int cnt = en - st;
        g_pooled[b * 256 + c] = ss / (float)(cnt > 0 ? cnt : 1);
        g_pooled[b * 256 + 128 + c] = mm;
    }
}

__global__ void k_cls(const float* __restrict__ g0,
                      const float* __restrict__ cw1, const float* __restrict__ cb1,
                      const float* __restrict__ cgm, const float* __restrict__ cbt,
                      const float* __restrict__ cw2, const float* __restrict__ cb2,
                      float* __restrict__ out) {
    __shared__ float zrow[8][264];
    __shared__ float h1[64][128];
    __shared__ float lg[64][2];
    int c = threadIdx.x;  // <<<1,128>>>

    for (int r0 = 0; r0 < 64; r0 += 8) {
        for (int idx = c; idx < 8 * 264; idx += 128) {
            int rr = idx / 264, k = idx - rr * 264;
            int r = r0 + rr;
            zrow[rr][k] = (k < 256) ? g_pooled[r * 256 + k] : g0[r * GF + (k - 256)];
        }
        __syncthreads();
        float acc[8];
#pragma unroll
        for (int rr = 0; rr < 8; rr++) acc[rr] = 0.f;
        for (int k = 0; k < 264; ++k) {
            float w = cw1[k * HD + c];
#pragma unroll
            for (int rr = 0; rr < 8; rr++) acc[rr] += zrow[rr][k] * w;
        }
        float bias = cb1[c];
#pragma unroll
        for (int rr = 0; rr < 8; rr++) h1[r0 + rr][c] = elu01(acc[rr] + bias);
        __syncthreads();
    }

    float s = 0.f, sq = 0.f;
    for (int r = 0; r < 64; r++) {
        float v = h1[r][c];
        s += v;
        sq += v * v;
    }
    float mean = s * (1.f / 64.f);
    float var = sq * (1.f / 64.f) - mean * mean;
    float a = cgm[c] * rsqrtf(var + BN_EPS);
    float bb = cbt[c] - mean * a;
    for (int r = 0; r < 64; r++) h1[r][c] = h1[r][c] * a + bb;
    __syncthreads();

    {
        int r = c >> 1, cls = c & 1;
        float l = cb2[cls];
        for (int k = 0; k < 128; k++) l += h1[r][k] * cw2[k * 2 + cls];
        lg[r][cls] = l;
    }
    __syncthreads();
    {
        int r = c >> 1, cls = c & 1;
        float l0 = lg[r][0], l1 = lg[r][1];
        float mx = fmaxf(l0, l1);
        float e0 = expf(l0 - mx), e1 = expf(l1 - mx);
        out[r * 2 + cls] = ((cls == 0) ? e0 : e1) / (e0 + e1);
    }
}

// ---------------- launch ----------------
extern "C" void kernel_launch(void* const* d_in, const int* in_sizes, int n_in,
                              void* d_out, int out_size) {
    const float* h0     = (const float*)d_in[0];
    const float* coord0 = (const float*)d_in[1];
    const float* g0     = (const float*)d_in[2];
    const int*   eidx   = (const int*)  d_in[3];
    const int*   batch  = (const int*)  d_in[4];
    const float* w1_0 = (const float*)d_in[5];
    const float* b1_0 = (const float*)d_in[6];
    const float* gm_0 = (const float*)d_in[7];
    const float* bt_0 = (const float*)d_in[8];
    const float* w2_0 = (const float*)d_in[9];
    const float* b2_0 = (const float*)d_in[10];
    const float* w1_r = (const float*)d_in[11];
    const float* b1_r = (const float*)d_in[12];
    const float* gm_r = (const float*)d_in[13];
    const float* bt_r = (const float*)d_in[14];
    const float* w2_r = (const float*)d_in[15];
    const float* b2_r = (const float*)d_in[16];
    const float* cw1  = (const float*)d_in[17];
    const float* cb1  = (const float*)d_in[18];
    const float* cgm  = (const float*)d_in[19];
    const float* cbt  = (const float*)d_in[20];
    const float* cw2  = (const float*)d_in[21];
    const float* cb2  = (const float*)d_in[22];

    const int* src = eidx;
    const int* dst = eidx + NE;

    float *xa19, *h, *xagg, *xA, *xB;
    cudaGetSymbolAddress((void**)&xa19, g_xa19);
    cudaGetSymbolAddress((void**)&h,    g_h);
    cudaGetSymbolAddress((void**)&xagg, g_xagg);
    cudaGetSymbolAddress((void**)&xA,   g_xA);
    cudaGetSymbolAddress((void**)&xB,   g_xB);

    cudaFuncSetAttribute(k_tgemm<true, true>,
                         cudaFuncAttributeMaxDynamicSharedMemorySize, TG_SMEM);
    cudaFuncSetAttribute(k_tgemm<false, false>,
                         cudaFuncAttributeMaxDynamicSharedMemorySize, TG_SMEM);

    const int GB = (NN + 127) / 128;   // 782

    // ---- CSR build ----
    k_zerodeg<<<(NN + 255) / 256, 256>>>();
    k_deg<<<(NE + 255) / 256, 256>>>(dst);
    k_scanA<<<SCAN_NBLK, SCAN_BS>>>();
    k_scanB<<<1, 32>>>();
    k_scanC<<<(NN + 255) / 256, 256>>>();
    k_fill<<<(NE + 255) / 256, 256>>>(src, dst);

    // ---- layer 0 ----
    k_concat<<<(NN * F20 + 255) / 256, 256>>>(h0, coord0);
    k_gather19<<<(NN + 7) / 8, 256>>>();
    k_zerostats<<<1, 256>>>();
    k_gemm19<<<GB, 256>>>(xa19, w1_0, b1_0, h);
    k_stats<<<512, 128>>>(h);
    k_bncoef<<<1, 128>>>(gm_0, bt_0);
    k_prepW<<<64, 256>>>(w2_0);
    k_tgemm<true, true><<<GB, 128, TG_SMEM>>>(h, b2_0, xA);

    // ---- layers 1..2 ----
    for (int i = 0; i < 2; i++) {
        const float* xin = (i == 0) ? xA : xB;
        float* xout      = (i == 0) ? xB : xA;
        k_gatherH<<<(NN + 7) / 8, 256>>>(xin, xagg);
        k_prepW<<<64, 256>>>(w1_r + i * HD * HD);
        k_tgemm<false, false><<<GB, 128, TG_SMEM>>>(xagg, b1_r + i * HD, h);
        k_zerostats<<<1, 256>>>();
        k_stats<<<512, 128>>>(h);
        k_bncoef<<<1, 128>>>(gm_r + i * HD, bt_r + i * HD);
        k_prepW<<<64, 256>>>(w2_r + i * HD * HD);
        k_tgemm<true, true><<<GB, 128, TG_SMEM>>>(h, b2_r + i * HD, xout);
    }

    // ---- pooling + classifier ----
    k_bounds<<<(NN + 255) / 256, 256>>>(batch);
    k_pool<<<NB, 512>>>(xA);
    k_cls<<<1, 128>>>(g0, cw1, cb1, cgm, cbt, cw2, cb2, (float*)d_out);
}

// round 11
// speedup vs baseline: 1.1992x; 1.1992x over previous
#include <cuda_runtime.h>
#include <math.h>
#include <stdint.h>

#define NN 100000
#define NE 1600000
#define NB 64
#define FI 16
#define HD 128
#define GF 8
#define F19 19
#define F20 20
#define BN_EPS 1e-5f
#define SCAN_BS 1024
#define SCAN_NBLK ((NN + SCAN_BS - 1) / SCAN_BS)   // 98
#define GH_SMEM 65536                               // k_gemmH dynamic smem

typedef unsigned long long ull;

// ---------------- scratch (device globals: allocation-free) ----------------
__device__ float g_x19 [NN * F20];
__device__ float g_xa19[NN * F20];
__device__ float g_h   [NN * HD];
__device__ float g_xagg[NN * HD];
__device__ float g_xA  [NN * HD];
__device__ float g_xB  [NN * HD];
__device__ float g_stats[2 * HD];
__device__ float g_coef [2 * HD];
__device__ int   g_ctr;
__device__ int   g_gstart[NB + 1];
__device__ float g_pooled[NB * 2 * HD];
// CSR scratch
__device__ int g_deg[NN];
__device__ int g_rowstart[NN + 1];
__device__ int g_cursor[NN];
__device__ int g_esrc[NE];
__device__ int g_bsum[SCAN_NBLK];

// ---------------- helpers ----------------
__device__ __forceinline__ float elu01(float v) {
    return v > 0.f ? v : 0.1f * expm1f(v);
}
__device__ __forceinline__ void ffma2(ull& d, ull a, ull b) {
    asm("fma.rn.f32x2 %0, %1, %2, %0;" : "+l"(d) : "l"(a), "l"(b));
}
__device__ __forceinline__ ull dup2(float a) {
    ull r; asm("mov.b64 %0, {%1, %1};" : "=l"(r) : "f"(a)); return r;
}
__device__ __forceinline__ ull pk2(float x, float y) {
    ull r; asm("mov.b64 %0, {%1, %2};" : "=l"(r) : "f"(x), "f"(y)); return r;
}
__device__ __forceinline__ float2 upk(ull v) {
    float2 f; asm("mov.b64 {%0, %1}, %2;" : "=f"(f.x), "=f"(f.y) : "l"(v)); return f;
}
__device__ __forceinline__ uint32_t smem_u32(const void* p) {
    return (uint32_t)__cvta_generic_to_shared(p);
}
__device__ __forceinline__ void cp16(uint32_t dst, const void* src) {
    asm volatile("cp.async.ca.shared.global [%0], [%1], 16;" :: "r"(dst), "l"(src) : "memory");
}

// shared stats->coef epilogue helper: call with scr[16*128] smem scratch
template <int GRID>
__device__ __forceinline__ void stats_epilogue(
    float* scr, const float* cS, const float* cQ, int tid, int tx, int ty,
    const float* gm, const float* bt) {
    __syncthreads();
#pragma unroll
    for (int c = 0; c < 8; c++) scr[ty * 128 + tx * 8 + c] = cS[c];
    __syncthreads();
    if (tid < 128) {
        float s = 0.f;
#pragma unroll
        for (int j = 0; j < 16; j++) s += scr[j * 128 + tid];
        atomicAdd(&g_stats[tid], s);
    }
    __syncthreads();
#pragma unroll
    for (int c = 0; c < 8; c++) scr[ty * 128 + tx * 8 + c] = cQ[c];
    __syncthreads();
    if (tid < 128) {
        float s = 0.f;
#pragma unroll
        for (int j = 0; j < 16; j++) s += scr[j * 128 + tid];
        atomicAdd(&g_stats[128 + tid], s);
    }
    // last-block computes BN coefficients and resets stats/counter
    __shared__ int s_last;
    __threadfence();
    __syncthreads();
    if (tid == 0) s_last = (atomicAdd(&g_ctr, 1) == GRID - 1) ? 1 : 0;
    __syncthreads();
    if (s_last) {
        __threadfence();
        if (tid < 128) {
            float mean = g_stats[tid] * (1.f / NN);
            float var = g_stats[128 + tid] * (1.f / NN) - mean * mean;
            float a = gm[tid] * rsqrtf(var + BN_EPS);
            g_coef[tid] = a;
            g_coef[128 + tid] = bt[tid] - mean * a;
            g_stats[tid] = 0.f;
            g_stats[128 + tid] = 0.f;
        }
        __threadfence();
        if (tid == 0) g_ctr = 0;
    }
}

// ---------------- CSR build ----------------
// bounds + zero all accumulators (first launch)
__global__ void k_bounds(const int* __restrict__ batch) {
    int i = blockIdx.x * blockDim.x + threadIdx.x;
    if (i < NN) g_deg[i] = 0;
    if (i < 256) g_stats[i] = 0.f;
    if (i == 0) g_ctr = 0;
    if (i >= NN) return;
    int cur = batch[i];
    int prev = (i == 0) ? -1 : batch[i - 1];
    for (int g = prev + 1; g <= cur; ++g) g_gstart[g] = i;
    if (i == NN - 1)
        for (int g = cur + 1; g <= NB; ++g) g_gstart[g] = NN;
}
__global__ void k_deg(const int* __restrict__ dst) {
    int e = blockIdx.x * blockDim.x + threadIdx.x;
    if (e < NE) atomicAdd(&g_deg[dst[e]], 1);
}
__global__ void k_scanA() {
    __shared__ int s[SCAN_BS];
    int i = blockIdx.x * SCAN_BS + threadIdx.x;
    int v = (i < NN) ? g_deg[i] : 0;
    s[threadIdx.x] = v;
    __syncthreads();
#pragma unroll
    for (int off = 1; off < SCAN_BS; off <<= 1) {
        int t = (threadIdx.x >= off) ? s[threadIdx.x - off] : 0;
        __syncthreads();
        s[threadIdx.x] += t;
        __syncthreads();
    }
    if (i < NN) g_rowstart[i] = s[threadIdx.x] - v;
    if (threadIdx.x == SCAN_BS - 1) g_bsum[blockIdx.x] = s[SCAN_BS - 1];
}
__global__ void k_scanB() {   // <<<1,32>>>
    int lane = threadIdx.x;
    int carry = 0;
    for (int b0 = 0; b0 < SCAN_NBLK; b0 += 32) {
        int i = b0 + lane;
        int orig = (i < SCAN_NBLK) ? g_bsum[i] : 0;
        int v = orig;
#pragma unroll
        for (int o = 1; o < 32; o <<= 1) {
            int t = __shfl_up_sync(0xFFFFFFFFu, v, o);
            if (lane >= o) v += t;
        }
        int total = __shfl_sync(0xFFFFFFFFu, v, 31);
        if (i < SCAN_NBLK) g_bsum[i] = v - orig + carry;
        carry += total;
    }
    if (lane == 0) g_rowstart[NN] = NE;
}
__global__ void k_scanC() {
    int i = blockIdx.x * blockDim.x + threadIdx.x;
    if (i < NN) {
        int r = g_rowstart[i] + g_bsum[i / SCAN_BS];
        g_rowstart[i] = r;
        g_cursor[i] = r;
    }
}
__global__ void k_fill(const int* __restrict__ src, const int* __restrict__ dst) {
    int e = blockIdx.x * blockDim.x + threadIdx.x;
    if (e < NE) {
        int pos = atomicAdd(&g_cursor[dst[e]], 1);
        g_esrc[pos] = src[e];
    }
}

// ---------------- feature prep + gather aggregation ----------------
__global__ void k_concat(const float* __restrict__ h0, const float* __restrict__ coord) {
    int i = blockIdx.x * blockDim.x + threadIdx.x;
    if (i >= NN * F20) return;
    int n = i / F20, j = i - n * F20;
    float v = 0.f;
    if (j < FI)        v = h0[n * FI + j];
    else if (j < F19)  v = coord[n * 3 + (j - FI)];
    g_x19[i] = v;
}

// dense mapping: 5 threads per node, each owns 4 cols
__global__ void k_gather19() {
    int i = blockIdx.x * blockDim.x + threadIdx.x;
    if (i >= NN * 5) return;
    int node = i / 5;
    int c = (i - node * 5) * 4;
    int st = g_rowstart[node], en = g_rowstart[node + 1];
    float4 v = *(const float4*)&g_x19[node * F20 + c];
    for (int e = st; e < en; e++) {
        int s = g_esrc[e];
        float4 u = *(const float4*)&g_x19[s * F20 + c];
        v.x += u.x; v.y += u.y; v.z += u.z; v.w += u.w;
    }
    *(float4*)&g_xa19[node * F20 + c] = v;
}

__global__ void k_gatherH(const float* __restrict__ x, float* __restrict__ xa) {
    int node = blockIdx.x * 8 + (threadIdx.x >> 5);
    if (node >= NN) return;
    int lane = threadIdx.x & 31;
    int st = g_rowstart[node], en = g_rowstart[node + 1];
    float4 v0 = *(const float4*)&x[node * HD + lane * 4];
    float4 v1 = make_float4(0.f, 0.f, 0.f, 0.f);
    int e = st;
    for (; e + 1 < en; e += 2) {
        int s0 = g_esrc[e], s1 = g_esrc[e + 1];
        float4 u0 = *(const float4*)&x[s0 * HD + lane * 4];
        float4 u1 = *(const float4*)&x[s1 * HD + lane * 4];
        v0.x += u0.x; v0.y += u0.y; v0.z += u0.z; v0.w += u0.w;
        v1.x += u1.x; v1.y += u1.y; v1.z += u1.z; v1.w += u1.w;
    }
    if (e < en) {
        int s0 = g_esrc[e];
        float4 u0 = *(const float4*)&x[s0 * HD + lane * 4];
        v0.x += u0.x; v0.y += u0.y; v0.z += u0.z; v0.w += u0.w;
    }
    v0.x += v1.x; v0.y += v1.y; v0.z += v1.z; v0.w += v1.w;
    *(float4*)&xa[node * HD + lane * 4] = v0;
}

// ---------------- H-GEMM: k-tile 32, double-buffered, cp.async B ----------------
// out[M,128] = act(A[M,128]) @ W[128,128] + bias
//  TRANS_A: BN scale/shift + relu on A load ; STATS: column stats + last-block coef ; ELU out
#define GB_H ((NN + 127) / 128)   // 782
template <bool TRANS_A, bool STATS, bool ELU>
__global__ void __launch_bounds__(256, 2)
k_gemmH(const float* __restrict__ A, const float* __restrict__ W,
        const float* __restrict__ bias,
        const float* __restrict__ gm, const float* __restrict__ bt,
        float* __restrict__ out) {
    extern __shared__ float sm[];
    float* Asm = sm;            // [2][32*128]
    float* Bsm = sm + 8192;     // [2][32*128]

    const int tid = threadIdx.x;
    const int tx = tid & 15;
    const int ty = tid >> 4;
    const int m0 = blockIdx.x * 128;
    const int ar = tid >> 1;             // A row owned (2 threads/row)
    const int aq0 = 4 * (tid & 1);       // col-quad base

    ull acc[8][4];
#pragma unroll
    for (int r = 0; r < 8; r++)
#pragma unroll
        for (int c = 0; c < 4; c++) acc[r][c] = 0ull;

    float4 pa[4];

    // prologue: tile 0
#pragma unroll
    for (int p = 0; p < 4; p++) {
        int grow = m0 + ar;
        pa[p] = (grow < NN) ? *(const float4*)&A[(size_t)grow * HD + (aq0 + p) * 4]
                            : make_float4(0.f, 0.f, 0.f, 0.f);
    }
#pragma unroll
    for (int p = 0; p < 4; p++) {
        int idx = p * 256 + tid;
        int kk = idx >> 5, n4 = idx & 31;
        cp16(smem_u32(&Bsm[kk * 128 + n4 * 4]), &W[(size_t)kk * HD + n4 * 4]);
    }
    asm volatile("cp.async.commit_group;" ::: "memory");
#pragma unroll
    for (int p = 0; p < 4; p++) {
        int q = aq0 + p;
        float4 v = pa[p];
        if (TRANS_A) {
            float4 ca = *(const float4*)&g_coef[q * 4];
            float4 cb = *(const float4*)&g_coef[128 + q * 4];
            v.x = fmaxf(fmaf(ca.x, v.x, cb.x), 0.f);
            v.y = fmaxf(fmaf(ca.y, v.y, cb.y), 0.f);
            v.z = fmaxf(fmaf(ca.z, v.z, cb.z), 0.f);
            v.w = fmaxf(fmaf(ca.w, v.w, cb.w), 0.f);
        }
        Asm[(q * 4 + 0) * 128 + ar] = v.x;
        Asm[(q * 4 + 1) * 128 + ar] = v.y;
        Asm[(q * 4 + 2) * 128 + ar] = v.z;
        Asm[(q * 4 + 3) * 128 + ar] = v.w;
    }
    asm volatile("cp.async.wait_group 0;" ::: "memory");
    __syncthreads();

#pragma unroll
    for (int kt = 0; kt < 4; kt++) {
        const float* Ac = Asm + (kt & 1) * 4096;
        const float* Bc = Bsm + (kt & 1) * 4096;
        if (kt < 3) {
            const int k0n = (kt + 1) * 32;
            float* Bn = Bsm + ((kt + 1) & 1) * 4096;
#pragma unroll
            for (int p = 0; p < 4; p++) {
                int idx = p * 256 + tid;
                int kk = idx >> 5, n4 = idx & 31;
                cp16(smem_u32(&Bn[kk * 128 + n4 * 4]), &W[(size_t)(k0n + kk) * HD + n4 * 4]);
            }
            asm volatile("cp.async.commit_group;" ::: "memory");
#pragma unroll
            for (int p = 0; p < 4; p++) {
                int grow = m0 + ar;
                pa[p] = (grow < NN)
                    ? *(const float4*)&A[(size_t)grow * HD + k0n + (aq0 + p) * 4]
                    : make_float4(0.f, 0.f, 0.f, 0.f);
            }
        }
#pragma unroll
        for (int k = 0; k < 32; k++) {
            float4 a0 = *(const float4*)&Ac[k * 128 + ty * 8];
            float4 a1 = *(const float4*)&Ac[k * 128 + ty * 8 + 4];
            float4 b0 = *(const float4*)&Bc[k * 128 + tx * 8];
            float4 b1 = *(const float4*)&Bc[k * 128 + tx * 8 + 4];
            ull bp0 = pk2(b0.x, b0.y), bp1 = pk2(b0.z, b0.w);
            ull bp2 = pk2(b1.x, b1.y), bp3 = pk2(b1.z, b1.w);
            float arr[8] = {a0.x, a0.y, a0.z, a0.w, a1.x, a1.y, a1.z, a1.w};
#pragma unroll
            for (int r = 0; r < 8; r++) {
                ull ap = dup2(arr[r]);
                ffma2(acc[r][0], ap, bp0);
                ffma2(acc[r][1], ap, bp1);
                ffma2(acc[r][2], ap, bp2);
                ffma2(acc[r][3], ap, bp3);
            }
        }
        if (kt < 3) {
            const int k0n = (kt + 1) * 32;
            float* An = Asm + ((kt + 1) & 1) * 4096;
#pragma unroll
            for (int p = 0; p < 4; p++) {
                int q = aq0 + p;
                float4 v = pa[p];
                if (TRANS_A) {
                    float4 ca = *(const float4*)&g_coef[k0n + q * 4];
                    float4 cb = *(const float4*)&g_coef[128 + k0n + q * 4];
                    v.x = fmaxf(fmaf(ca.x, v.x, cb.x), 0.f);
                    v.y = fmaxf(fmaf(ca.y, v.y, cb.y), 0.f);
                    v.z = fmaxf(fmaf(ca.z, v.z, cb.z), 0.f);
                    v.w = fmaxf(fmaf(ca.w, v.w, cb.w), 0.f);
                }
                An[(q * 4 + 0) * 128 + ar] = v.x;
                An[(q * 4 + 1) * 128 + ar] = v.y;
                An[(q * 4 + 2) * 128 + ar] = v.z;
                An[(q * 4 + 3) * 128 + ar] = v.w;
            }
            asm volatile("cp.async.wait_group 0;" ::: "memory");
        }
        __syncthreads();
    }

    // ---- epilogue ----
    float4 bb0 = *(const float4*)&bias[tx * 8];
    float4 bb1 = *(const float4*)&bias[tx * 8 + 4];
    float bv[8] = {bb0.x, bb0.y, bb0.z, bb0.w, bb1.x, bb1.y, bb1.z, bb1.w};

    float cS[8], cQ[8];
    if (STATS) {
#pragma unroll
        for (int c = 0; c < 8; c++) { cS[c] = 0.f; cQ[c] = 0.f; }
    }
#pragma unroll
    for (int r = 0; r < 8; r++) {
        int grow = m0 + ty * 8 + r;
        if (grow < NN) {
            float2 p0 = upk(acc[r][0]), p1 = upk(acc[r][1]);
            float2 p2 = upk(acc[r][2]), p3 = upk(acc[r][3]);
            float v[8] = {p0.x, p0.y, p1.x, p1.y, p2.x, p2.y, p3.x, p3.y};
#pragma unroll
            for (int c = 0; c < 8; c++) {
                v[c] += bv[c];
                if (STATS) { cS[c] += v[c]; cQ[c] += v[c] * v[c]; }
                if (ELU) v[c] = elu01(v[c]);
            }
            *(float4*)&out[(size_t)grow * HD + tx * 8]     = make_float4(v[0], v[1], v[2], v[3]);
            *(float4*)&out[(size_t)grow * HD + tx * 8 + 4] = make_float4(v[4], v[5], v[6], v[7]);
        }
    }
    if (STATS)
        stats_epilogue<GB_H>(Asm, cS, cQ, tid, tx, ty, gm, bt);
}

// ---------------- FFMA2 GEMM (layer-0, K=19) with stats + coef ----------------
__device__ __forceinline__ void ld_tiles19(const float* __restrict__ A,
                                           const float* __restrict__ W,
                                           int m0, int k0, int tid,
                                           float4* pa, float4* pw) {
#pragma unroll
    for (int p = 0; p < 2; p++) {
        int idx = tid * 2 + p;
        int r = idx >> 2, kq = idx & 3;
        int gk = k0 + kq * 4, grow = m0 + r;
        float4 v = make_float4(0.f, 0.f, 0.f, 0.f);
        if (grow < NN && gk < F19) v = *(const float4*)&A[(size_t)grow * F20 + gk];
        pa[p] = v;
        int kk = idx >> 5, n4 = idx & 31;
        float4 w = make_float4(0.f, 0.f, 0.f, 0.f);
        if (k0 + kk < F19) w = *(const float4*)&W[(size_t)(k0 + kk) * HD + n4 * 4];
        pw[p] = w;
    }
}
__device__ __forceinline__ void st_tiles19(float* __restrict__ As, float* __restrict__ Bs,
                                           int tid, const float4* pa, const float4* pw) {
#pragma unroll
    for (int p = 0; p < 2; p++) {
        int idx = tid * 2 + p;
        int r = idx >> 2, kq = idx & 3;
        float4 v = pa[p];
        As[(kq * 4 + 0) * 128 + r] = v.x;
        As[(kq * 4 + 1) * 128 + r] = v.y;
        As[(kq * 4 + 2) * 128 + r] = v.z;
        As[(kq * 4 + 3) * 128 + r] = v.w;
        int kk = idx >> 5, n4 = idx & 31;
        *(float4*)&Bs[kk * 128 + n4 * 4] = pw[p];
    }
}

__global__ void __launch_bounds__(256, 2)
k_gemm19(const float* __restrict__ A, const float* __restrict__ W,
         const float* __restrict__ bias,
         const float* __restrict__ gm, const float* __restrict__ bt,
         float* __restrict__ out) {
    __shared__ float As[2][16 * 128];
    __shared__ float Bs[2][16 * 128];
    const int tid = threadIdx.x;
    const int tx = tid & 15;
    const int ty = tid >> 4;
    const int m0 = blockIdx.x * 128;

    ull acc[8][4];
#pragma unroll
    for (int r = 0; r < 8; r++)
#pragma unroll
        for (int c = 0; c < 4; c++) acc[r][c] = 0ull;

    float4 pa[2], pw[2];
    ld_tiles19(A, W, m0, 0, tid, pa, pw);
    st_tiles19(As[0], Bs[0], tid, pa, pw);
    __syncthreads();

#pragma unroll
    for (int kt = 0; kt < 2; kt++) {
        const float* Ac = As[kt & 1];
        const float* Bc = Bs[kt & 1];
        if (kt == 0) ld_tiles19(A, W, m0, 16, tid, pa, pw);
#pragma unroll
        for (int k = 0; k < 16; k++) {
            float4 a0 = *(const float4*)&Ac[k * 128 + ty * 8];
            float4 a1 = *(const float4*)&Ac[k * 128 + ty * 8 + 4];
            float4 b0 = *(const float4*)&Bc[k * 128 + tx * 8];
            float4 b1 = *(const float4*)&Bc[k * 128 + tx * 8 + 4];
            ull bp0 = pk2(b0.x, b0.y), bp1 = pk2(b0.z, b0.w);
            ull bp2 = pk2(b1.x, b1.y), bp3 = pk2(b1.z, b1.w);
            float arr[8] = {a0.x, a0.y, a0.z, a0.w, a1.x, a1.y, a1.z, a1.w};
#pragma unroll
            for (int r = 0; r < 8; r++) {
                ull ap = dup2(arr[r]);
                ffma2(acc[r][0], ap, bp0);
                ffma2(acc[r][1], ap, bp1);
                ffma2(acc[r][2], ap, bp2);
                ffma2(acc[r][3], ap, bp3);
            }
        }
        if (kt == 0) st_tiles19(As[1], Bs[1], tid, pa, pw);
        __syncthreads();
    }

    float4 bb0 = *(const float4*)&bias[tx * 8];
    float4 bb1 = *(const float4*)&bias[tx * 8 + 4];
    float bv[8] = {bb0.x, bb0.y, bb0.z, bb0.w, bb1.x, bb1.y, bb1.z, bb1.w};
    float cS[8], cQ[8];
#pragma unroll
    for (int c = 0; c < 8; c++) { cS[c] = 0.f; cQ[c] = 0.f; }
#pragma unroll
    for (int r = 0; r < 8; r++) {
        int grow = m0 + ty * 8 + r;
        if (grow < NN) {
            float2 p0 = upk(acc[r][0]), p1 = upk(acc[r][1]);
            float2 p2 = upk(acc[r][2]), p3 = upk(acc[r][3]);
            float v[8] = {p0.x, p0.y, p1.x, p1.y, p2.x, p2.y, p3.x, p3.y};
#pragma unroll
            for (int c = 0; c < 8; c++) {
                v[c] += bv[c];
                cS[c] += v[c]; cQ[c] += v[c] * v[c];
            }
            *(float4*)&out[(size_t)grow * HD + tx * 8]     = make_float4(v[0], v[1], v[2], v[3]);
            *(float4*)&out[(size_t)grow * HD + tx * 8 + 4] = make_float4(v[4], v[5], v[6], v[7]);
        }
    }
    stats_epilogue<GB_H>(As[0], cS, cQ, tid, tx, ty, gm, bt);
}

// ---------------- pooling / classifier ----------------
__global__ void k_pool(const float* __restrict__ x) {
    __shared__ float ps[4][128];
    __shared__ float pm[4][128];
    int b = blockIdx.x;
    int rg = threadIdx.x >> 7, c = threadIdx.x & 127;
    int st = g_gstart[b], en = g_gstart[b + 1];
    float s = 0.f, m = -INFINITY;
    for (int r = st + rg; r < en; r += 4) {
        float v = x[(size_t)r * HD + c];
        s += v;
        m = fmaxf(m, v);
    }
    ps[rg][c] = s;
    pm[rg][c] = m;
    __syncthreads();
    if (rg == 0) {
        float ss = ps[0][c] + ps[1][c] + ps[2][c] + ps[3][c];
        float mm = fmaxf(fmaxf(pm[0][c], pm[1][c]), fmaxf(pm[2][c], pm[3][c]));
        int cnt = en - st;
        g_pooled[b * 256 + c] = ss / (float)(cnt > 0 ? cnt : 1);
        g_pooled[b * 256 + 128 + c] = mm;
    }
}

__global__ void k_cls(const float* __restrict__ g0,
                      const float* __restrict__ cw1, const float* __restrict__ cb1,
                      const float* __restrict__ cgm, const float* __restrict__ cbt,
                      const float* __restrict__ cw2, const float* __restrict__ cb2,
                      float* __restrict__ out) {
    __shared__ float zrow[8][264];
    __shared__ float h1[64][128];
    __shared__ float lg[64][2];
    int c = threadIdx.x;  // <<<1,128>>>

    for (int r0 = 0; r0 < 64; r0 += 8) {
        for (int idx = c; idx < 8 * 264; idx += 128) {
            int rr = idx / 264, k = idx - rr * 264;
            int r = r0 + rr;
            zrow[rr][k] = (k < 256) ? g_pooled[r * 256 + k] : g0[r * GF + (k - 256)];
        }
        __syncthreads();
        float acc[8];
#pragma unroll
        for (int rr = 0; rr < 8; rr++) acc[rr] = 0.f;
        for (int k = 0; k < 264; ++k) {
            float w = cw1[k * HD + c];
#pragma unroll
            for (int rr = 0; rr < 8; rr++) acc[rr] += zrow[rr][k] * w;
        }
        float bias = cb1[c];
#pragma unroll
        for (int rr = 0; rr < 8; rr++) h1[r0 + rr][c] = elu01(acc[rr] + bias);
        __syncthreads();
    }

    float s = 0.f, sq = 0.f;
    for (int r = 0; r < 64; r++) {
        float v = h1[r][c];
        s += v;
        sq += v * v;
    }
    float mean = s * (1.f / 64.f);
    float var = sq * (1.f / 64.f) - mean * mean;
    float a = cgm[c] * rsqrtf(var + BN_EPS);
    float bb = cbt[c] - mean * a;
    for (int r = 0; r < 64; r++) h1[r][c] = h1[r][c] * a + bb;
    __syncthreads();

    {
        int r = c >> 1, cls = c & 1;
        float l = cb2[cls];
        for (int k = 0; k < 128; k++) l += h1[r][k] * cw2[k * 2 + cls];
        lg[r][cls] = l;
    }
    __syncthreads();
    {
        int r = c >> 1, cls = c & 1;
        float l0 = lg[r][0], l1 = lg[r][1];
        float mx = fmaxf(l0, l1);
        float e0 = expf(l0 - mx), e1 = expf(l1 - mx);
        out[r * 2 + cls] = ((cls == 0) ? e0 : e1) / (e0 + e1);
    }
}

// ---------------- launch ----------------
extern "C" void kernel_launch(void* const* d_in, const int* in_sizes, int n_in,
                              void* d_out, int out_size) {
    const float* h0     = (const float*)d_in[0];
    const float* coord0 = (const float*)d_in[1];
    const float* g0     = (const float*)d_in[2];
    const int*   eidx   = (const int*)  d_in[3];
    const int*   batch  = (const int*)  d_in[4];
    const float* w1_0 = (const float*)d_in[5];
    const float* b1_0 = (const float*)d_in[6];
    const float* gm_0 = (const float*)d_in[7];
    const float* bt_0 = (const float*)d_in[8];
    const float* w2_0 = (const float*)d_in[9];
    const float* b2_0 = (const float*)d_in[10];
    const float* w1_r = (const float*)d_in[11];
    const float* b1_r = (const float*)d_in[12];
    const float* gm_r = (const float*)d_in[13];
    const float* bt_r = (const float*)d_in[14];
    const float* w2_r = (const float*)d_in[15];
    const float* b2_r = (const float*)d_in[16];
    const float* cw1  = (const float*)d_in[17];
    const float* cb1  = (const float*)d_in[18];
    const float* cgm  = (const float*)d_in[19];
    const float* cbt  = (const float*)d_in[20];
    const float* cw2  = (const float*)d_in[21];
    const float* cb2  = (const float*)d_in[22];

    const int* src = eidx;
    const int* dst = eidx + NE;

    float *xa19, *h, *xagg, *xA, *xB;
    cudaGetSymbolAddress((void**)&xa19, g_xa19);
    cudaGetSymbolAddress((void**)&h,    g_h);
    cudaGetSymbolAddress((void**)&xagg, g_xagg);
    cudaGetSymbolAddress((void**)&xA,   g_xA);
    cudaGetSymbolAddress((void**)&xB,   g_xB);

    cudaFuncSetAttribute(k_gemmH<true, false, true>,
                         cudaFuncAttributeMaxDynamicSharedMemorySize, GH_SMEM);
    cudaFuncSetAttribute(k_gemmH<false, true, false>,
                         cudaFuncAttributeMaxDynamicSharedMemorySize, GH_SMEM);

    // ---- CSR build (+ zeroing fused into k_bounds) ----
    k_bounds<<<(NN + 255) / 256, 256>>>(batch);
    k_deg<<<(NE + 255) / 256, 256>>>(dst);
    k_scanA<<<SCAN_NBLK, SCAN_BS>>>();
    k_scanB<<<1, 32>>>();
    k_scanC<<<(NN + 255) / 256, 256>>>();
    k_fill<<<(NE + 255) / 256, 256>>>(src, dst);

    // ---- layer 0 ----
    k_concat<<<(NN * F20 + 255) / 256, 256>>>(h0, coord0);
    k_gather19<<<(NN * 5 + 255) / 256, 256>>>();
    k_gemm19<<<GB_H, 256>>>(xa19, w1_0, b1_0, gm_0, bt_0, h);
    k_gemmH<true, false, true><<<GB_H, 256, GH_SMEM>>>(h, w2_0, b2_0, nullptr, nullptr, xA);

    // ---- layers 1..2 ----
    for (int i = 0; i < 2; i++) {
        const float* xin = (i == 0) ? xA : xB;
        float* xout      = (i == 0) ? xB : xA;
        k_gatherH<<<(NN + 7) / 8, 256>>>(xin, xagg);
        k_gemmH<false, true, false><<<GB_H, 256, GH_SMEM>>>(
            xagg, w1_r + i * HD * HD, b1_r + i * HD, gm_r + i * HD, bt_r + i * HD, h);
        k_gemmH<true, false, true><<<GB_H, 256, GH_SMEM>>>(
            h, w2_r + i * HD * HD, b2_r + i * HD, nullptr, nullptr, xout);
    }

    // ---- pooling + classifier ----
    k_pool<<<NB, 512>>>(xA);
    k_cls<<<1, 128>>>(g0, cw1, cb1, cgm, cbt, cw2, cb2, (float*)d_out);
}